// round 14
// baseline (speedup 1.0000x reference)
#include <cuda_runtime.h>
#include <cuda_bf16.h>

// Problem constants (match reference)
#define SIZE     16384      // 128*128 points per batch
#define KNN      16
#define ND       5          // num derivatives (order 2, 2D)
#define NBATCH   32
#define CHUNKS   4          // CTAs per batch -> grid 128 (single wave)
#define CTA_PTS  (SIZE / CHUNKS)   // 4096 points per CTA
#define NTHREADS 1024
#define PTS_PER_THREAD (CTA_PTS / NTHREADS)  // 4

// Dynamic smem: uint2 {packed unorm16 coords, f32 value bits} per point (128KB)
#define SMEM_BYTES (SIZE * sizeof(uint2))   // 131072

// Unit-scale constants: coordinates in "x65535" units inside the solve.
// Columns scale by c = {B, B, 2B^2, B^2, 2B^2} (B = 65535) vs the reference
// Taylor design -> ridge scales by c_i^2, output weights by c_i. Exact algebra.
#define RIDGE_B2  4294.836225f       // 1e-6 * 65535^2
#define RIDGE_B4  1.8445618e13f      // 1e-6 * 65535^4
#define RIDGE_4B4 7.3782473e13f      // 4e-6 * 65535^4
#define WSC_B     65535.0f
#define WSC_B2    4294836225.0f      // 65535^2
#define FBIAS     0x4B000000u        // float bits of 2^23

__device__ __forceinline__ float frcp_fast(float x) {
    float r; asm("rcp.approx.f32 %0, %1;" : "=f"(r) : "f"(x)); return r;
}
__device__ __forceinline__ void prefetch_l2(const void* p) {
    asm volatile("prefetch.global.L2 [%0];" :: "l"(p));
}
// Decode packed unorm16 pair -> biased floats (2^23 + u). Differences of two
// biased values are exact integer-valued floats in [-65535, 65535].
__device__ __forceinline__ float dec_x(unsigned p) {
    return __uint_as_float(__byte_perm(p, FBIAS, 0x7610));
}
__device__ __forceinline__ float dec_y(unsigned p) {
    return __uint_as_float(__byte_perm(p, FBIAS, 0x7632));
}

// ---------------------------------------------------------------------------
// Primary kernel: grid 128 (single wave), batch in 128 KB smem as interleaved
// {packed coords, value} records. Software rotate (next point's group-0 stream
// in registers) + L2 prefetch of the stream two points ahead.
// ---------------------------------------------------------------------------
__global__ void __launch_bounds__(NTHREADS, 1)
tp_layer_smem_kernel(const float* __restrict__ x,
                     const float* __restrict__ points,
                     const int*   __restrict__ edge_index,
                     const float* __restrict__ dt_p,
                     const float* __restrict__ dist,
                     const float* __restrict__ weight,
                     float* __restrict__ out)
{
    extern __shared__ uint2 spv[];   // [SIZE] {packed unorm16 xy, f32 value bits}

    const int b     = blockIdx.x / CHUNKS;
    const int chunk = blockIdx.x % CHUNKS;
    const int tid   = threadIdx.x;

    const int s_base = chunk * CTA_PTS;
    const int4*   ei_base = reinterpret_cast<const int4*>(edge_index + (size_t)b * SIZE * KNN);
    const float4* dw_base = reinterpret_cast<const float4*>(dist       + (size_t)b * SIZE * KNN);
    // group g of point s lives at [s*4 + g] in int4/float4 units

    // Early prologue (independent of smem -> overlaps staging + barrier):
    // register-prefetch point 0's group 0, L2-prefetch point 1's streams.
    const int s0 = s_base + tid;
    int4   nei = ei_base[(size_t)s0 * 4];
    float4 ndw = dw_base[(size_t)s0 * 4];
    prefetch_l2(ei_base + (size_t)(s0 + NTHREADS) * 4);
    prefetch_l2(dw_base + (size_t)(s0 + NTHREADS) * 4);

    const float* pts_b = points + (size_t)b * SIZE * 2;
    const float* x_b   = x + (size_t)b * SIZE;

    // Stage: per 2 points read float4 coords + float2 values, quantize coords
    // to unorm16, emit one uint4 (STS.128, conflict-free).
    {
        const float4* srcp = reinterpret_cast<const float4*>(pts_b);  // 2 pts
        const float2* srcx = reinterpret_cast<const float2*>(x_b);    // 2 vals
        uint4* dst = reinterpret_cast<uint4*>(spv);                   // 2 recs
        #pragma unroll
        for (int i = 0; i < (SIZE / 2) / NTHREADS; ++i) {             // 8 iters
            const int k = tid + i * NTHREADS;
            const float4 f = srcp[k];
            const float2 v = srcx[k];
            const unsigned x0 = __float2uint_rn(f.x * 65535.0f);
            const unsigned y0 = __float2uint_rn(f.y * 65535.0f);
            const unsigned x1 = __float2uint_rn(f.z * 65535.0f);
            const unsigned y1 = __float2uint_rn(f.w * 65535.0f);
            dst[k] = make_uint4(x0 | (y0 << 16), __float_as_uint(v.x),
                                x1 | (y1 << 16), __float_as_uint(v.y));
        }
    }
    __syncthreads();

    const float dt = dt_p[0];
    float wf[ND];
    wf[0] = weight[0] * WSC_B;        wf[1] = weight[1] * WSC_B;
    wf[2] = 2.f * weight[2] * WSC_B2; wf[3] = weight[3] * WSC_B2;
    wf[4] = 2.f * weight[4] * WSC_B2;

    #pragma unroll 1
    for (int p = 0; p < PTS_PER_THREAD; ++p) {
        const int s = s_base + tid + p * NTHREADS;

        // L2 prefetch of the stream TWO points ahead (~700 cyc of cover for
        // the 577-cyc DRAM latency). No regs, no scoreboard.
        if (p + 2 < PTS_PER_THREAD) {
            const int sp = s + 2 * NTHREADS;
            prefetch_l2(ei_base + (size_t)sp * 4);
            prefetch_l2(dw_base + (size_t)sp * 4);
        }

        const uint2 pcv = spv[s];
        const float cx = dec_x(pcv.x), cy = dec_y(pcv.x);
        const float vc = __uint_as_float(pcv.y);

        float M20=0,M11=0,M02=0;                 // degree-2 monomials
        float M30=0,M21=0,M12=0,M03=0;           // degree-3
        float M40=0,M31=0,M22=0,M13=0,M04=0;     // degree-4
        float b0=0,b1=0,b2=0,b3=0,b4=0;          // rhs

        auto do4 = [&](const int4 ei, const float4 dw) {
            const int   idx[4] = {ei.x, ei.y, ei.z, ei.w};
            const float wts[4] = {dw.x, dw.y, dw.z, dw.w};
            #pragma unroll
            for (int j = 0; j < 4; ++j) {
                const float w  = wts[j];
                const uint2 pv = spv[idx[j]];   // single LDS.64: coords + value
                const float dx = dec_x(pv.x) - cx;   // exact, in B units
                const float dy = dec_y(pv.x) - cy;
                const float vn = __uint_as_float(pv.y);
                const float p0 = dx * w;
                const float p1 = dy * w;
                const float q0 = p0 * dx;
                const float q1 = p0 * dy;
                const float q2 = p1 * dy;
                const float r  = (vn - vc) * w;
                M20 = fmaf(p0, p0, M20); M11 = fmaf(p0, p1, M11); M02 = fmaf(p1, p1, M02);
                M30 = fmaf(q0, p0, M30); M21 = fmaf(q0, p1, M21);
                M12 = fmaf(q1, p1, M12); M03 = fmaf(q2, p1, M03);
                M40 = fmaf(q0, q0, M40); M31 = fmaf(q0, q1, M31); M22 = fmaf(q0, q2, M22);
                M13 = fmaf(q1, q2, M13); M04 = fmaf(q2, q2, M04);
                b0 = fmaf(p0, r, b0); b1 = fmaf(p1, r, b1);
                b2 = fmaf(q0, r, b2); b3 = fmaf(q1, r, b3); b4 = fmaf(q2, r, b4);
            }
        };

        // group 0 from prefetched registers; groups 1..3 streamed inline
        do4(nei, ndw);
        #pragma unroll
        for (int g = 1; g < 4; ++g)
            do4(ei_base[(size_t)s * 4 + g], dw_base[(size_t)s * 4 + g]);

        // Rotate: prefetch NEXT point's group 0 before the solve (guarded).
        if (p + 1 < PTS_PER_THREAD) {
            const int sn = s + NTHREADS;
            nei = ei_base[(size_t)sn * 4];
            ndw = dw_base[(size_t)sn * 4];
        }

        // Upper-triangular Gram matrix + unit-scaled ridge.
        float m[ND][ND];
        m[0][0]=M20+RIDGE_B2; m[0][1]=M11; m[0][2]=M30; m[0][3]=M21; m[0][4]=M12;
        m[1][1]=M02+RIDGE_B2; m[1][2]=M21; m[1][3]=M12; m[1][4]=M03;
        m[2][2]=M40+RIDGE_4B4; m[2][3]=M31; m[2][4]=M22;
        m[3][3]=M22+RIDGE_B4;  m[3][4]=M13;
        m[4][4]=M04+RIDGE_4B4;
        float bv[ND] = {b0, b1, b2, b3, b4};

        // symmetric unpivoted Gaussian elimination (upper triangle only)
        #pragma unroll
        for (int i = 0; i < ND - 1; ++i) {
            const float inv = frcp_fast(m[i][i]);
            #pragma unroll
            for (int r2 = i + 1; r2 < ND; ++r2) {
                const float f = m[i][r2] * inv;
                #pragma unroll
                for (int c = r2; c < ND; ++c) m[r2][c] = fmaf(-f, m[i][c], m[r2][c]);
                bv[r2] = fmaf(-f, bv[i], bv[r2]);
            }
        }
        // back substitution; accumulate du with folded weights
        float sol[ND];
        float du = 0.f;
        #pragma unroll
        for (int i = ND - 1; i >= 0; --i) {
            float acc = bv[i];
            #pragma unroll
            for (int c = i + 1; c < ND; ++c) acc = fmaf(-m[i][c], sol[c], acc);
            sol[i] = acc * frcp_fast(m[i][i]);
            du = fmaf(sol[i], wf[i], du);
        }

        out[(size_t)b * SIZE + s] = vc + dt * du;
    }
}

// ---------------------------------------------------------------------------
// Fallback kernel (global-memory gathers, full fp32) — env insurance only
// ---------------------------------------------------------------------------
__global__ void __launch_bounds__(256)
tp_layer_fallback_kernel(const float* __restrict__ x,
                         const float* __restrict__ points,
                         const int*   __restrict__ edge_index,
                         const float* __restrict__ dt_p,
                         const float* __restrict__ dist,
                         const float* __restrict__ weight,
                         float* __restrict__ out,
                         int total)
{
    int gid = blockIdx.x * blockDim.x + threadIdx.x;
    if (gid >= total) return;
    const int b = gid >> 14;
    const int s = gid & (SIZE - 1);

    const float* pts_b = points + (size_t)b * SIZE * 2;
    const float* x_b   = x + (size_t)b * SIZE;
    const float2 pc = *reinterpret_cast<const float2*>(pts_b + 2 * s);
    const float  vc = x_b[s];

    const int4*   ei4 = reinterpret_cast<const int4*>(edge_index + (size_t)b * SIZE * KNN + (size_t)s * KNN);
    const float4* dw4 = reinterpret_cast<const float4*>(dist       + (size_t)b * SIZE * KNN + (size_t)s * KNN);

    float M20=0,M11=0,M02=0,M30=0,M21=0,M12=0,M03=0,M40=0,M31=0,M22=0,M13=0,M04=0;
    float b0=0,b1=0,b2=0,b3=0,b4=0;
    #pragma unroll
    for (int g = 0; g < 4; ++g) {
        const int4   ei = ei4[g];
        const float4 dw = dw4[g];
        const int   idx[4] = {ei.x, ei.y, ei.z, ei.w};
        const float wts[4] = {dw.x, dw.y, dw.z, dw.w};
        #pragma unroll
        for (int j = 0; j < 4; ++j) {
            const int id = idx[j];
            const float2 pn = *reinterpret_cast<const float2*>(pts_b + 2 * id);
            const float dx = pn.x - pc.x, dy = pn.y - pc.y;
            const float w = wts[j];
            const float p0 = dx*w, p1 = dy*w;
            const float q0 = p0*dx, q1 = p0*dy, q2 = p1*dy;
            const float r = (x_b[id] - vc) * w;
            M20 = fmaf(p0,p0,M20); M11 = fmaf(p0,p1,M11); M02 = fmaf(p1,p1,M02);
            M30 = fmaf(q0,p0,M30); M21 = fmaf(q0,p1,M21);
            M12 = fmaf(q1,p1,M12); M03 = fmaf(q2,p1,M03);
            M40 = fmaf(q0,q0,M40); M31 = fmaf(q0,q1,M31); M22 = fmaf(q0,q2,M22);
            M13 = fmaf(q1,q2,M13); M04 = fmaf(q2,q2,M04);
            b0 = fmaf(p0,r,b0); b1 = fmaf(p1,r,b1);
            b2 = fmaf(q0,r,b2); b3 = fmaf(q1,r,b3); b4 = fmaf(q2,r,b4);
        }
    }
    float m[ND][ND];
    m[0][0]=M20+1e-6f; m[0][1]=M11; m[0][2]=M30; m[0][3]=M21; m[0][4]=M12;
    m[1][1]=M02+1e-6f; m[1][2]=M21; m[1][3]=M12; m[1][4]=M03;
    m[2][2]=M40+4e-6f; m[2][3]=M31; m[2][4]=M22;
    m[3][3]=M22+1e-6f; m[3][4]=M13;
    m[4][4]=M04+4e-6f;
    float bv[ND] = {b0, b1, b2, b3, b4};
    #pragma unroll
    for (int i = 0; i < ND - 1; ++i) {
        const float inv = frcp_fast(m[i][i]);
        #pragma unroll
        for (int r2 = i + 1; r2 < ND; ++r2) {
            const float f = m[i][r2] * inv;
            #pragma unroll
            for (int c = r2; c < ND; ++c) m[r2][c] = fmaf(-f, m[i][c], m[r2][c]);
            bv[r2] = fmaf(-f, bv[i], bv[r2]);
        }
    }
    float sol[ND];
    float du = 0.f;
    const float wfl[ND] = {weight[0], weight[1], 2.f*weight[2], weight[3], 2.f*weight[4]};
    #pragma unroll
    for (int i = ND - 1; i >= 0; --i) {
        float acc = bv[i];
        #pragma unroll
        for (int c = i + 1; c < ND; ++c) acc = fmaf(-m[i][c], sol[c], acc);
        sol[i] = acc * frcp_fast(m[i][i]);
        du = fmaf(sol[i], wfl[i], du);
    }
    out[gid] = vc + dt_p[0] * du;
}

extern "C" void kernel_launch(void* const* d_in, const int* in_sizes, int n_in,
                              void* d_out, int out_size)
{
    const float* x      = (const float*)d_in[0];
    const float* points = (const float*)d_in[1];
    const int*   eidx   = (const int*)  d_in[2];
    const float* dt     = (const float*)d_in[3];
    const float* dist   = (const float*)d_in[4];
    const float* weight = (const float*)d_in[5];
    float* out = (float*)d_out;

    // Opt-in smem; environment-deterministic, identical on every call.
    cudaError_t attr_ok = cudaFuncSetAttribute(
        tp_layer_smem_kernel,
        cudaFuncAttributeMaxDynamicSharedMemorySize,
        SMEM_BYTES);

    if (attr_ok == cudaSuccess) {
        tp_layer_smem_kernel<<<NBATCH * CHUNKS, NTHREADS, SMEM_BYTES>>>(
            x, points, eidx, dt, dist, weight, out);
    } else {
        const int total = out_size;
        tp_layer_fallback_kernel<<<(total + 255) / 256, 256>>>(
            x, points, eidx, dt, dist, weight, out, total);
    }
}